// round 12
// baseline (speedup 1.0000x reference)
#include <cuda_runtime.h>
#include <math.h>

#define GDIM 4
#define SDIM 2048
#define TTOT 8192
#define MDIM 1024
#define EDIM 64
#define GEMM_SMS 32                  // dedicated gemm SMs
#define GEMM_BLOCKS 128              // = GEMM_SMS * OCC, 64 tokens each
#define OCC 4
#define CHUNK_F4 16384               // 256KB fill chunks

typedef unsigned long long ull;

__device__ int      g_idx[TTOT];
__device__ float    g_gate[TTOT];
__device__ int      g_pos[TTOT];
__device__ int      g_counts[GDIM * EDIM];
__device__ float    g_proxy[GEMM_BLOCKS * EDIM];
__device__ unsigned g_route_done, g_pos_done, g_chunk_next, g_chunks_done;

__global__ void k_reset() {
    g_route_done = 0; g_pos_done = 0; g_chunk_next = 0; g_chunks_done = 0;
}

__device__ __forceinline__ void spin_until(unsigned* ctr, unsigned tgt) {
    if (threadIdx.x == 0) {
        while (atomicAdd(ctr, 0u) < tgt) __nanosleep(256);
    }
    __syncthreads();
    __threadfence();
}

// Work-stealing zero-fill: block drains 256KB chunks until exhausted.
__device__ __forceinline__ void drain_fill(float4* o4, size_t n4, unsigned* s_chunk) {
    const int tid = threadIdx.x;
    unsigned done = 0;
    const float4 z = make_float4(0.f, 0.f, 0.f, 0.f);
    for (;;) {
        if (tid == 0) *s_chunk = atomicAdd(&g_chunk_next, 1u);
        __syncthreads();
        unsigned ck = *s_chunk;
        __syncthreads();
        size_t lo = (size_t)ck * CHUNK_F4;
        if (lo >= n4) break;
        size_t hi = lo + CHUNK_F4; if (hi > n4) hi = n4;
        size_t i = lo + tid;
        for (; i + 768 < hi; i += 1024) {
            __stcs(o4 + i, z);
            __stcs(o4 + i + 256, z);
            __stcs(o4 + i + 512, z);
            __stcs(o4 + i + 768, z);
        }
        for (; i < hi; i += 256) __stcs(o4 + i, z);
        ++done;
    }
    __threadfence();
    __syncthreads();
    if (tid == 0 && done) atomicAdd(&g_chunks_done, done);
}

// ---------------------------------------------------------------------------
// Persistent kernel, one wave (4 blocks/SM on every SM).
// SM-partitioned roles via bid%nsm (one-wave placement: smid = LUT[bid%nsm]):
//   s <  32 : gemm block gid = s*4 + r   (32 SMs run ONLY gemm -> no issue
//             contention from fill warps), then pos/aux, then join fill, patch.
//   s >= 32 : work-stealing fill, exit.
// ---------------------------------------------------------------------------
__global__ __launch_bounds__(256, OCC)
void k_fused(const float* __restrict__ x, const float* __restrict__ Wt,
             float* __restrict__ out, int C, size_t N, unsigned nchunks, int nsm) {
    __shared__ __align__(16) char sm_raw[33664];
    __shared__ unsigned s_chunk;
    const int tid = threadIdx.x;
    const int s = blockIdx.x % nsm;
    const int r = blockIdx.x / nsm;
    const size_t n4 = (2 * N) >> 2;
    float4* o4 = (float4*)out;

    // ===================== FILL ROLE =====================
    if (s >= GEMM_SMS) {
        drain_fill(o4, n4, &s_chunk);
        return;
    }
    const int gid = s * OCC + r;        // 0..127

    // ===================== GEMM ROLE =====================
    {
        float* xls  = (float*)sm_raw;        // 64*65
        float* ws   = xls + 64 * 65;         // 64*64
        float* isum = ws + 64 * 64;          // 64

        const int w = tid >> 5;
        const int l = tid & 31;
        const int tb = gid * 64;

        ull acc[2][4] = {};

        for (int ch = 0; ch < 16; ++ch) {
            {
                int t = tid >> 2, q = tid & 3;
                const float4* src = (const float4*)(x + (size_t)(tb + t) * MDIM + ch * 64 + q * 16);
                float4 v0 = src[0], v1 = src[1], v2 = src[2], v3 = src[3];
                float* d = &xls[t * 65 + q * 16];
                d[0]=v0.x; d[1]=v0.y; d[2]=v0.z; d[3]=v0.w;
                d[4]=v1.x; d[5]=v1.y; d[6]=v1.z; d[7]=v1.w;
                d[8]=v2.x; d[9]=v2.y; d[10]=v2.z; d[11]=v2.w;
                d[12]=v3.x; d[13]=v3.y; d[14]=v3.z; d[15]=v3.w;
            }
            {
                const float4* src = (const float4*)(Wt + (size_t)(ch * 64) * EDIM);
                float4* dst = (float4*)ws;
#pragma unroll
                for (int j = 0; j < 4; ++j) dst[tid + j * 256] = src[tid + j * 256];
            }
            __syncthreads();

#pragma unroll 4
            for (int mm = 0; mm < 64; ++mm) {
                float xa = xls[l * 65 + mm];
                float xb = xls[(l + 32) * 65 + mm];
                ull xa2, xb2;
                asm("mov.b64 %0, {%1, %1};" : "=l"(xa2) : "f"(xa));
                asm("mov.b64 %0, {%1, %1};" : "=l"(xb2) : "f"(xb));
                const ull* wp = (const ull*)&ws[mm * 64 + w * 8];
#pragma unroll
                for (int p = 0; p < 4; ++p) {
                    ull w2 = wp[p];
                    asm("fma.rn.f32x2 %0, %1, %2, %0;" : "+l"(acc[0][p]) : "l"(w2), "l"(xa2));
                    asm("fma.rn.f32x2 %0, %1, %2, %0;" : "+l"(acc[1][p]) : "l"(w2), "l"(xb2));
                }
            }
            __syncthreads();
        }

#pragma unroll
        for (int tt = 0; tt < 2; ++tt) {
            int t = l + 32 * tt;
#pragma unroll
            for (int p = 0; p < 4; ++p) {
                float lo, hi;
                asm("mov.b64 {%0, %1}, %2;" : "=f"(lo), "=f"(hi) : "l"(acc[tt][p]));
                xls[t * 65 + w * 8 + 2 * p]     = lo;
                xls[t * 65 + w * 8 + 2 * p + 1] = hi;
            }
        }
        __syncthreads();

        if (tid < 64) {
            const int t = tid;
            float mx = -1e30f; int am = 0;
            for (int e = 0; e < EDIM; ++e) {
                float v = xls[t * 65 + e];
                if (v > mx) { mx = v; am = e; }
            }
            float sm = 0.0f;
            for (int e = 0; e < EDIM; ++e) {
                float p = expf(xls[t * 65 + e] - mx);
                xls[t * 65 + e] = p;
                sm += p;
            }
            float inv = 1.0f / sm;
            isum[t] = inv;
            g_idx[tb + t]  = am;
            g_gate[tb + t] = inv;
        }
        __syncthreads();

        if (tid < 64) {
            const int e = tid;
            float sa = 0.0f;
            for (int t = 0; t < 64; ++t) sa += xls[t * 65 + e] * isum[t];
            g_proxy[gid * 64 + e] = sa;
        }
        __threadfence();
        __syncthreads();
        if (tid == 0) atomicAdd(&g_route_done, 1u);
    }

    // ============ POS SCAN (gid 0..3, one group each) ============
    if (gid < GDIM) {
        spin_until(&g_route_done, GEMM_BLOCKS);
        int* idx_s = (int*)sm_raw;          // 2048
        int* cnt_s = idx_s + 2048;          // 1024
        int* pos_s = cnt_s + 1024;          // 2048
        const int g = gid;

        for (int i = tid; i < 2048; i += 256) idx_s[i] = __ldcg(&g_idx[g * 2048 + i]);
        __syncthreads();

#pragma unroll
        for (int k = 0; k < 4; ++k) {
            int wi = tid + 256 * k;
            int c = wi >> 6, e = wi & 63;
            int cnt = 0;
#pragma unroll 8
            for (int i = 0; i < 128; ++i) cnt += (idx_s[c * 128 + i] == e);
            cnt_s[c * 64 + e] = cnt;
        }
        __syncthreads();

#pragma unroll
        for (int k = 0; k < 4; ++k) {
            int wi = tid + 256 * k;
            int c = wi >> 6, e = wi & 63;
            int pre = 0;
            for (int cc = 0; cc < c; ++cc) pre += cnt_s[cc * 64 + e];
            if (c == 15) g_counts[g * 64 + e] = pre + cnt_s[c * 64 + e];
            int run = pre;
            for (int i = 0; i < 128; ++i) {
                int sp = c * 128 + i;
                if (idx_s[sp] == e) pos_s[sp] = run++;
            }
        }
        __syncthreads();

        for (int i = tid; i < 2048; i += 256) g_pos[g * 2048 + i] = pos_s[i];
        __threadfence();
        __syncthreads();
        if (tid == 0) atomicAdd(&g_pos_done, 1u);
    }

    // ============ AUX LOSS (gid 0) ============
    if (gid == 0) {
        spin_until(&g_pos_done, GDIM);
        float* red = (float*)sm_raw;
        const int g = tid >> 6;
        const int e = tid & 63;
        float px = 0.0f;
        for (int bb = 0; bb < 32; ++bb) px += __ldcg(&g_proxy[(g * 32 + bb) * 64 + e]);
        const float denom = 1.0f + 1e-6f;
        float d1 = ((float)__ldcg(&g_counts[g * 64 + e]) / (float)SDIM) / denom;
        float dp = (px / (float)SDIM) / denom;
        red[tid] = d1 * dp;
        __syncthreads();
        for (int st = 128; st > 0; st >>= 1) {
            if (tid < st) red[tid] += red[tid + st];
            __syncthreads();
        }
        if (tid == 0)
            out[2 * N] = (red[0] / 256.0f) * ((float)EDIM * (float)EDIM * 0.01f);
    }

    // ============ JOIN THE FILL (gemm SMs after compute) ============
    drain_fill(o4, n4, &s_chunk);

    // ============ PATCH (own 64 tokens) ============
    spin_until(&g_pos_done, GDIM);
    spin_until(&g_chunks_done, nchunks);
    if (tid < 64) {
        int t = gid * 64 + tid;
        int p = __ldcg(&g_pos[t]);
        if (p < C) {
            int e = __ldcg(&g_idx[t]);
            float gv = __ldcg(&g_gate[t]);
            size_t base = ((size_t)t * EDIM + e) * (size_t)C + p;
            out[base]     = gv;
            out[N + base] = 1.0f;
        }
    }
}

// ---------------------------------------------------------------------------
static int get_nsm() {
    static int nsm = 0;
    if (nsm == 0) {
        cudaDeviceGetAttribute(&nsm, cudaDevAttrMultiProcessorCount, 0);
        if (nsm <= GEMM_SMS) nsm = GEMM_SMS + 1;   // paranoia
    }
    return nsm;
}

extern "C" void kernel_launch(void* const* d_in, const int* in_sizes, int n_in,
                              void* d_out, int out_size) {
    const float* x  = (const float*)d_in[0];
    const float* Wt = (const float*)d_in[1];
    float* out = (float*)d_out;

    size_t N = ((size_t)out_size - 1) / 2;
    int C = (int)(N / ((size_t)TTOT * EDIM));   // 160

    size_t n4 = (2 * N) >> 2;
    unsigned nchunks = (unsigned)((n4 + CHUNK_F4 - 1) / CHUNK_F4);   // 2560

    int nsm = get_nsm();                 // 152 on GB300
    int grid = OCC * nsm;                // one co-resident wave

    k_reset<<<1, 1>>>();
    k_fused<<<grid, 256>>>(x, Wt, out, C, N, nchunks, nsm);
}

// round 13
// speedup vs baseline: 1.2196x; 1.2196x over previous
#include <cuda_runtime.h>
#include <math.h>

#define GDIM 4
#define SDIM 2048
#define TTOT 8192
#define MDIM 1024
#define EDIM 64
#define NBLK 256          // gemm blocks: 32 tokens each

typedef unsigned long long ull;

__device__ int   g_idx[TTOT];
__device__ float g_gate[TTOT];
__device__ int   g_pos[TTOT];
__device__ int   g_counts[GDIM * EDIM];
__device__ float g_proxy[NBLK * EDIM];

// ---------------------------------------------------------------------------
// K1: logits = x @ W (fp32, f32x2 FFMA), softmax, argmax, proxy sums.
// 256 blocks x 32 tokens -> all 148 SMs busy, shorter per-block critical path.
// Warp w -> experts [8w,8w+8) as 4 f32x2 pairs (LDS.64 uniform broadcast),
// lane l -> token l. m accumulation strictly sequential (ch then mm) ->
// bit-identical logits to the R6 kernel.
// ---------------------------------------------------------------------------
__global__ __launch_bounds__(256, 4)
void k_gemm(const float* __restrict__ x, const float* __restrict__ Wt) {
    __shared__ __align__(16) float xls[32 * 65];   // x chunk; then logits/probs
    __shared__ __align__(16) float ws[64 * 64];    // W chunk [m][e]
    __shared__ float isum[32];

    const int tid = threadIdx.x;
    const int w = tid >> 5;
    const int l = tid & 31;
    const int tb = blockIdx.x * 32;

    ull acc[4] = {};   // 4 expert-pairs (f32x2)

    for (int ch = 0; ch < 16; ++ch) {
        // stage x: 32 tokens x 64 m. thread -> token tid>>3, 8 floats.
        {
            int t = tid >> 3, q = tid & 7;
            const float4* src = (const float4*)(x + (size_t)(tb + t) * MDIM + ch * 64 + q * 8);
            float4 v0 = src[0], v1 = src[1];
            float* d = &xls[t * 65 + q * 8];
            d[0]=v0.x; d[1]=v0.y; d[2]=v0.z; d[3]=v0.w;
            d[4]=v1.x; d[5]=v1.y; d[6]=v1.z; d[7]=v1.w;
        }
        // stage W chunk: 64 m x 64 e, linear copy (1024 float4 / 256 thr)
        {
            const float4* src = (const float4*)(Wt + (size_t)(ch * 64) * EDIM);
            float4* dst = (float4*)ws;
#pragma unroll
            for (int j = 0; j < 4; ++j) dst[tid + j * 256] = src[tid + j * 256];
        }
        __syncthreads();

#pragma unroll 8
        for (int mm = 0; mm < 64; ++mm) {
            float xa = xls[l * 65 + mm];
            ull xa2;
            asm("mov.b64 %0, {%1, %1};" : "=l"(xa2) : "f"(xa));
            const ull* wp = (const ull*)&ws[mm * 64 + w * 8];
#pragma unroll
            for (int p = 0; p < 4; ++p) {
                ull w2 = wp[p];                       // LDS.64, warp-uniform
                asm("fma.rn.f32x2 %0, %1, %2, %0;" : "+l"(acc[p]) : "l"(w2), "l"(xa2));
            }
        }
        __syncthreads();
    }

    // logits -> smem
#pragma unroll
    for (int p = 0; p < 4; ++p) {
        float lo, hi;
        asm("mov.b64 {%0, %1}, %2;" : "=f"(lo), "=f"(hi) : "l"(acc[p]));
        xls[l * 65 + w * 8 + 2 * p]     = lo;
        xls[l * 65 + w * 8 + 2 * p + 1] = hi;
    }
    __syncthreads();

    // softmax / argmax: one thread per token
    if (tid < 32) {
        const int t = tid;
        float mx = -1e30f; int am = 0;
        for (int e = 0; e < EDIM; ++e) {
            float v = xls[t * 65 + e];
            if (v > mx) { mx = v; am = e; }     // first-max semantics
        }
        float sm = 0.0f;
        for (int e = 0; e < EDIM; ++e) {
            float p = expf(xls[t * 65 + e] - mx);
            xls[t * 65 + e] = p;
            sm += p;
        }
        float inv = 1.0f / sm;
        isum[t] = inv;
        g_idx[tb + t]  = am;
        g_gate[tb + t] = inv;      // p_argmax = 1/sum
    }
    __syncthreads();

    // per-block proxy sums over the 32 tokens
    if (tid < 64) {
        const int e = tid;
        float s = 0.0f;
        for (int t = 0; t < 32; ++t) s += xls[t * 65 + e] * isum[t];
        g_proxy[blockIdx.x * 64 + e] = s;
    }
}

// ---------------------------------------------------------------------------
// K2: exclusive running position within each (group, expert).
// ---------------------------------------------------------------------------
__global__ __launch_bounds__(1024, 1)
void k_pos() {
    __shared__ int idx_s[2048];
    __shared__ int cnt_s[16 * 64];
    __shared__ int pos_s[2048];

    const int g = blockIdx.x;
    const int tid = threadIdx.x;

    idx_s[tid]        = g_idx[g * 2048 + tid];
    idx_s[tid + 1024] = g_idx[g * 2048 + tid + 1024];
    __syncthreads();

    const int c = tid >> 6;
    const int e = tid & 63;

    int cnt = 0;
#pragma unroll 8
    for (int i = 0; i < 128; ++i) cnt += (idx_s[c * 128 + i] == e);
    cnt_s[c * 64 + e] = cnt;
    __syncthreads();

    int pre = 0;
    for (int cc = 0; cc < c; ++cc) pre += cnt_s[cc * 64 + e];
    if (c == 15) g_counts[g * 64 + e] = pre + cnt;

    int run = pre;
#pragma unroll 4
    for (int i = 0; i < 128; ++i) {
        int s = c * 128 + i;
        if (idx_s[s] == e) pos_s[s] = run++;
    }
    __syncthreads();

    g_pos[g * 2048 + tid]        = pos_s[tid];
    g_pos[g * 2048 + tid + 1024] = pos_s[tid + 1024];
}

// ---------------------------------------------------------------------------
// K3: fused fill + scatter + aux (identical to the 146.2us R6 kernel,
// except aux reads 64 proxy blocks per group).
// Block r in [0, 2*TTOT): one output row (token x section), 40KB contiguous,
// nonzero patched inline. Block 2*TTOT: aux loss.
// ---------------------------------------------------------------------------
__global__ __launch_bounds__(256, 8)
void k_fill(float* __restrict__ out, int C, size_t N) {
    const int r = blockIdx.x;
    const int tid = threadIdx.x;

    if (r < 2 * TTOT) {
        const int sec = (r >= TTOT);
        const int t = sec ? r - TTOT : r;

        const int p = g_pos[t];
        const int tgt = (p < C) ? (g_idx[t] * C + p) : -1;
        const float val = sec ? 1.0f : g_gate[t];
        const int tf4 = tgt >> 2;

        float4* row = (float4*)(out + (size_t)sec * N + (size_t)t * (size_t)(EDIM * C));
        const int nf4 = (EDIM * C) >> 2;                 // 2560 for C=160

        for (int f = tid; f < nf4; f += 256) {
            float4 v = make_float4(0.f, 0.f, 0.f, 0.f);
            if (f == tf4) ((float*)&v)[tgt & 3] = val;
            __stcs(row + f, v);
        }
    } else {
        __shared__ float red[256];
        const int g = tid >> 6;
        const int e = tid & 63;
        float px = 0.0f;
        for (int b = 0; b < 64; ++b) px += g_proxy[(g * 64 + b) * 64 + e];
        const float denom = 1.0f + 1e-6f;
        float d1 = ((float)g_counts[g * 64 + e] / (float)SDIM) / denom;
        float dp = (px / (float)SDIM) / denom;
        red[tid] = d1 * dp;
        __syncthreads();
        for (int s = 128; s > 0; s >>= 1) {
            if (tid < s) red[tid] += red[tid + s];
            __syncthreads();
        }
        if (tid == 0)
            out[2 * N] = (red[0] / 256.0f) * ((float)EDIM * (float)EDIM * 0.01f);
    }
}

// ---------------------------------------------------------------------------
extern "C" void kernel_launch(void* const* d_in, const int* in_sizes, int n_in,
                              void* d_out, int out_size) {
    const float* x  = (const float*)d_in[0];
    const float* Wt = (const float*)d_in[1];
    float* out = (float*)d_out;

    size_t N = ((size_t)out_size - 1) / 2;
    int C = (int)(N / ((size_t)TTOT * EDIM));   // 160

    k_gemm<<<NBLK, 256>>>(x, Wt);
    k_pos<<<GDIM, 1024>>>();
    k_fill<<<2 * TTOT + 1, 256>>>(out, C, N);
}